// round 1
// baseline (speedup 1.0000x reference)
#include <cuda_runtime.h>
#include <cstdint>
#include <cstdio>

#define NMAX 100000

// Scratch (static __device__ arrays; allocation-free per harness rules)
__device__ float g_NS[(size_t)NMAX * 832];   // [N][832]: [0:64]=n(node enc), [64 + r*96 + k]=S (scatter sums)
__device__ float g_cat[(size_t)NMAX * 128];  // [N][128]: [0:64]=h2 (layer2 out), [64:128]=o (omega enc)
__device__ float g_h[(size_t)NMAX * 64];     // layer-1 output
__device__ float g_M[(size_t)NMAX * 512];    // M[n][r*64+j] = h[n] @ W2[r]
__device__ float g_buf[(size_t)NMAX * 512];  // per-(dst,rel) max buffers (0xFF = empty sentinel)
__device__ float g_tmp[(size_t)NMAX * 64];   // h @ Wroot2 + b2
__device__ float g_t2[(size_t)NMAX * 64];    // relu(cat @ Wagg + bagg)
__device__ float g_Wc1[832 * 64];            // [Wroot1 ; W1 flattened]
__device__ float g_Wc2[64 * 512];            // W2 transposed to [k][r*64+j]

// ---------------- packed f32x2 helpers ----------------
__device__ __forceinline__ unsigned long long bcast2(float b) {
    unsigned long long r;
    asm("mov.b64 %0, {%1, %1};" : "=l"(r) : "r"(__float_as_uint(b)));
    return r;
}
__device__ __forceinline__ void fma2(unsigned long long& d, unsigned long long a, unsigned long long b) {
    asm("fma.rn.f32x2 %0, %1, %2, %0;" : "+l"(d) : "l"(a), "l"(b));
}
__device__ __forceinline__ float lo32(unsigned long long v) { return __uint_as_float((unsigned)v); }
__device__ __forceinline__ float hi32(unsigned long long v) { return __uint_as_float((unsigned)(v >> 32)); }

__device__ __forceinline__ void atomicMaxF(float* a, float v) {
    if (v >= 0.f) atomicMax((int*)a, __float_as_int(v));
    else          atomicMin((unsigned int*)a, __float_as_uint(v));
}

// ---------------- init: zero S region, fill max-buffers with sentinel ----------------
__global__ void k_init(int N) {
    size_t i = (size_t)blockIdx.x * blockDim.x + threadIdx.x;
    size_t n1 = (size_t)N * 832 / 4;
    size_t n2 = (size_t)N * 512 / 4;
    if (i < n1) {
        ((float4*)g_NS)[i] = make_float4(0.f, 0.f, 0.f, 0.f);
    } else if (i < n1 + n2) {
        ((uint4*)g_buf)[i - n1] = make_uint4(~0u, ~0u, ~0u, ~0u);
    }
}

// ---------------- build combined weight matrices ----------------
__global__ void k_prep(const float* __restrict__ Wroot1, const float* __restrict__ W1,
                       const float* __restrict__ W2) {
    int i = blockIdx.x * 256 + threadIdx.x;
    if (i < 832 * 64) {
        int row = i >> 6, j = i & 63;
        float v;
        if (row < 64) v = Wroot1[row * 64 + j];
        else          v = W1[(row - 64) * 64 + j];   // row-64 = r*96+k, W1 flat [(r*96+k)*64+j]
        g_Wc1[i] = v;
    }
    if (i < 64 * 512) {
        int k = i >> 9, c = i & 511;
        int r = c >> 6, j = c & 63;
        g_Wc2[i] = W2[(r * 64 + k) * 64 + j];
    }
}

// ---------------- node encoders: n -> g_NS[:,0:64], o -> g_cat[:,64:128] ----------------
__global__ void k_encode(const float* __restrict__ x, const float* __restrict__ omega,
                         const float* __restrict__ Wn, const float* __restrict__ bn,
                         const float* __restrict__ Wo, const float* __restrict__ bo, int N) {
    int i = blockIdx.x * 256 + threadIdx.x;
    if (i >= N * 64) return;
    int d = i >> 6, j = i & 63;
    float x0 = __ldg(x + d * 3), x1 = __ldg(x + d * 3 + 1), x2 = __ldg(x + d * 3 + 2);
    float nv = fmaf(x0, __ldg(Wn + j), fmaf(x1, __ldg(Wn + 64 + j), fmaf(x2, __ldg(Wn + 128 + j), __ldg(bn + j))));
    g_NS[(size_t)d * 832 + j] = fmaxf(nv, 0.f);
    float o0 = __ldg(omega + d * 2), o1 = __ldg(omega + d * 2 + 1);
    float ov = fmaf(o0, __ldg(Wo + j), fmaf(o1, __ldg(Wo + 64 + j), __ldg(bo + j)));
    g_cat[(size_t)d * 128 + 64 + j] = fmaxf(ov, 0.f);
}

// ---------------- edge pass 1: scatter-add n[src] and e(edge) into S[dst][r] ----------------
__global__ void k_edge1(const int* __restrict__ ei, const float* __restrict__ ea,
                        const int* __restrict__ et, const float* __restrict__ We,
                        const float* __restrict__ be, int E) {
    int gw = (blockIdx.x * blockDim.x + threadIdx.x) >> 5;
    if (gw >= E) return;
    int lane = threadIdx.x & 31;
    int src = __ldg(ei + gw);
    int dst = __ldg(ei + E + gw);
    int r   = __ldg(et + gw);
    float* Sd = g_NS + (size_t)dst * 832 + 64 + r * 96;
    if (lane < 16) {
        // n[src] contribution: 64 floats, 4 per lane, vector atomics
        float4 v = *(const float4*)(g_NS + (size_t)src * 832 + lane * 4);
        atomicAdd((float4*)(Sd + lane * 4), v);
    } else {
        // e = relu(edge_attr @ We + be): 32 floats, 2 per lane
        int j = (lane - 16) * 2;
        float a0 = __ldg(ea + 2 * gw), a1 = __ldg(ea + 2 * gw + 1);
        float e0 = fmaxf(fmaf(a0, __ldg(We + j),     fmaf(a1, __ldg(We + 32 + j),     __ldg(be + j))),     0.f);
        float e1 = fmaxf(fmaf(a0, __ldg(We + j + 1), fmaf(a1, __ldg(We + 32 + j + 1), __ldg(be + j + 1))), 0.f);
        atomicAdd((float2*)(Sd + 64 + j), make_float2(e0, e1));
    }
}

// ---------------- edge pass 2: gather M[src][r], atomicMax into buf[dst][r] ----------------
__global__ void k_edge2(const int* __restrict__ ei, const int* __restrict__ et, int E) {
    int gw = (blockIdx.x * blockDim.x + threadIdx.x) >> 5;
    if (gw >= E) return;
    int lane = threadIdx.x & 31;
    int src = __ldg(ei + gw);
    int dst = __ldg(ei + E + gw);
    int r   = __ldg(et + gw);
    const float* Mp = g_M + (size_t)src * 512 + r * 64;
    float v0 = __ldg(Mp + lane), v1 = __ldg(Mp + lane + 32);
    float* bp = g_buf + (size_t)dst * 512 + r * 64;
    atomicMaxF(bp + lane, v0);
    atomicMaxF(bp + lane + 32, v1);
}

// ---------------- generic tiled SGEMM: C[M, cols] = A[M,K] @ B[K, cols] (+bias, relu) ----------------
// 64 rows x NC cols per block, 256 threads, 4x(NC/16) register tile, packed f32x2 FMAs.
template <int NC>
__global__ void __launch_bounds__(256) k_gemm(
    const float* __restrict__ A, int lda, int K,
    const float* __restrict__ B, int ldb,
    const float* __restrict__ bias, int relu,
    float* __restrict__ C, int ldc, int M)
{
    constexpr int TN = NC / 16;
    __shared__ __align__(16) float As[16 * 66];   // As[k*66 + row], pad 66 -> conflict-free
    __shared__ __align__(16) float Bs[16 * NC];   // Bs[k*NC + c]
    int tid = threadIdx.x;
    int tx = tid & 15, ty = tid >> 4;
    int row0 = blockIdx.x * 64;
    int col0 = blockIdx.y * NC;
    unsigned long long acc[2][TN];
#pragma unroll
    for (int i = 0; i < 2; i++)
#pragma unroll
        for (int c = 0; c < TN; c++) acc[i][c] = 0ull;

    for (int kc = 0; kc < K; kc += 16) {
#pragma unroll
        for (int it = 0; it < 4; it++) {
            int idx = tid + it * 256;
            int rr = idx >> 4, k = idx & 15;
            int grow = row0 + rr;
            As[k * 66 + rr] = (grow < M) ? A[(size_t)grow * lda + kc + k] : 0.f;
        }
#pragma unroll
        for (int it = 0; it < NC / 16; it++) {
            int idx = tid + it * 256;
            int k = idx / NC, c = idx % NC;
            Bs[idx] = B[(size_t)(kc + k) * ldb + col0 + c];
        }
        __syncthreads();
#pragma unroll
        for (int k = 0; k < 16; k++) {
            unsigned long long a01 = *(const unsigned long long*)&As[k * 66 + ty * 4];
            unsigned long long a23 = *(const unsigned long long*)&As[k * 66 + ty * 4 + 2];
#pragma unroll
            for (int c0 = 0; c0 < TN; c0 += 4) {
                float4 bv = *(const float4*)&Bs[k * NC + tx * TN + c0];
                unsigned long long p0 = bcast2(bv.x), p1 = bcast2(bv.y);
                unsigned long long p2 = bcast2(bv.z), p3 = bcast2(bv.w);
                fma2(acc[0][c0 + 0], a01, p0); fma2(acc[1][c0 + 0], a23, p0);
                fma2(acc[0][c0 + 1], a01, p1); fma2(acc[1][c0 + 1], a23, p1);
                fma2(acc[0][c0 + 2], a01, p2); fma2(acc[1][c0 + 2], a23, p2);
                fma2(acc[0][c0 + 3], a01, p3); fma2(acc[1][c0 + 3], a23, p3);
            }
        }
        __syncthreads();
    }
    int colb = col0 + tx * TN;
#pragma unroll
    for (int i = 0; i < 2; i++) {
#pragma unroll
        for (int p = 0; p < 2; p++) {
            int row = row0 + ty * 4 + i * 2 + p;
            if (row >= M) continue;
#pragma unroll
            for (int c0 = 0; c0 < TN; c0 += 4) {
                float4 v;
                float* vp = (float*)&v;
#pragma unroll
                for (int cc = 0; cc < 4; cc++) {
                    unsigned long long a = acc[i][c0 + cc];
                    float f = p ? hi32(a) : lo32(a);
                    if (bias) f += __ldg(bias + colb + c0 + cc);
                    if (relu) f = fmaxf(f, 0.f);
                    vp[cc] = f;
                }
                *(float4*)&C[(size_t)row * ldc + colb + c0] = v;
            }
        }
    }
}

// ---------------- layer-2 combine: h2 = relu(tmp + sum_r nonempty(buf)) ----------------
__global__ void k_f2(int N) {
    int i = blockIdx.x * 256 + threadIdx.x;
    if (i >= N * 64) return;
    int d = i >> 6, j = i & 63;
    float acc = g_tmp[i];
    const unsigned* bu = (const unsigned*)(g_buf + (size_t)d * 512 + j);
#pragma unroll
    for (int r = 0; r < 8; r++) {
        unsigned u = bu[r * 64];
        if (u != 0xFFFFFFFFu) acc += __uint_as_float(u);
    }
    g_cat[(size_t)d * 128 + j] = fmaxf(acc, 0.f);
}

// ---------------- head: out = tanh(t2 . Wc + bc) * 5 ----------------
__global__ void k_f4(const float* __restrict__ Wc, const float* __restrict__ bc,
                     float* __restrict__ out, int N) {
    int w = (blockIdx.x * blockDim.x + threadIdx.x) >> 5;
    if (w >= N) return;
    int lane = threadIdx.x & 31;
    const float* t = g_t2 + (size_t)w * 64;
    float p = t[lane] * __ldg(Wc + lane) + t[lane + 32] * __ldg(Wc + lane + 32);
#pragma unroll
    for (int off = 16; off > 0; off >>= 1) p += __shfl_xor_sync(0xffffffffu, p, off);
    if (lane == 0) out[w] = tanhf(p + __ldg(bc)) * 5.f;
}

extern "C" void kernel_launch(void* const* d_in, const int* in_sizes, int n_in,
                              void* d_out, int out_size) {
    const float* x      = (const float*)d_in[0];
    const int*   ei     = (const int*)  d_in[1];
    const float* ea     = (const float*)d_in[2];
    const int*   et     = (const int*)  d_in[3];
    const float* omega  = (const float*)d_in[4];
    const float* Wn     = (const float*)d_in[5];
    const float* bn     = (const float*)d_in[6];
    const float* We     = (const float*)d_in[7];
    const float* be     = (const float*)d_in[8];
    const float* Wo     = (const float*)d_in[9];
    const float* bo     = (const float*)d_in[10];
    const float* W1     = (const float*)d_in[11];
    const float* Wroot1 = (const float*)d_in[12];
    const float* b1     = (const float*)d_in[13];
    const float* W2     = (const float*)d_in[14];
    const float* Wroot2 = (const float*)d_in[15];
    const float* b2     = (const float*)d_in[16];
    const float* Wagg   = (const float*)d_in[17];
    const float* bagg   = (const float*)d_in[18];
    const float* Wc     = (const float*)d_in[19];
    const float* bc     = (const float*)d_in[20];
    float* out = (float*)d_out;

    int N = in_sizes[0] / 3;
    int E = in_sizes[3];
    if (N > NMAX) N = NMAX;

    float *pNS, *ph, *pM, *pcat, *ptmp, *pt2, *pWc1, *pWc2;
    cudaGetSymbolAddress((void**)&pNS,  g_NS);
    cudaGetSymbolAddress((void**)&ph,   g_h);
    cudaGetSymbolAddress((void**)&pM,   g_M);
    cudaGetSymbolAddress((void**)&pcat, g_cat);
    cudaGetSymbolAddress((void**)&ptmp, g_tmp);
    cudaGetSymbolAddress((void**)&pt2,  g_t2);
    cudaGetSymbolAddress((void**)&pWc1, g_Wc1);
    cudaGetSymbolAddress((void**)&pWc2, g_Wc2);

    // 1) init scratch (zero S, sentinel-fill max buffers)
    size_t initTotal = ((size_t)N * 832 + (size_t)N * 512) / 4;
    k_init<<<(unsigned)((initTotal + 255) / 256), 256>>>(N);
    // 2) combined weights
    k_prep<<<(832 * 64 + 255) / 256, 256>>>(Wroot1, W1, W2);
    // 3) node encoders
    k_encode<<<(N * 64 + 255) / 256, 256>>>(x, omega, Wn, bn, Wo, bo, N);
    // 4) layer-1 scatter (sum aggregation factored through linear map)
    k_edge1<<<(E + 7) / 8, 256>>>(ei, ea, et, We, be, E);
    // 5) layer-1 dense: h = relu([n|S] @ [Wroot1;W1] + b1)
    k_gemm<64><<<dim3((N + 63) / 64, 1), 256>>>(pNS, 832, 832, pWc1, 64, b1, 1, ph, 64, N);
    // 6) layer-2 message precompute: M = h @ W2[all r]
    k_gemm<128><<<dim3((N + 63) / 64, 4), 256>>>(ph, 64, 64, pWc2, 512, nullptr, 0, pM, 512, N);
    // 7) layer-2 scatter-max
    k_edge2<<<(E + 7) / 8, 256>>>(ei, et, E);
    // 8) root term: tmp = h @ Wroot2 + b2
    k_gemm<64><<<dim3((N + 63) / 64, 1), 256>>>(ph, 64, 64, Wroot2, 64, b2, 0, ptmp, 64, N);
    // 9) combine maxes + relu -> cat[:,0:64]
    k_f2<<<(N * 64 + 255) / 256, 256>>>(N);
    // 10) t2 = relu(cat @ Wagg + bagg)
    k_gemm<64><<<dim3((N + 63) / 64, 1), 256>>>(pcat, 128, 128, Wagg, 64, bagg, 1, pt2, 64, N);
    // 11) head
    k_f4<<<(N + 7) / 8, 256>>>(Wc, bc, out, N);
}

// round 4
// speedup vs baseline: 1.2661x; 1.2661x over previous
#include <cuda_runtime.h>
#include <cstdint>
#include <cfloat>

#define NMAX 100000
#define EMAX 1600000

// ---------------- scratch (static __device__, allocation-free) ----------------
__device__ float g_NS[(size_t)NMAX * 832];   // [N][832]: [0:64]=n enc, [64+r*96 ..]=S per-rel sums
__device__ float g_cat[(size_t)NMAX * 128];  // [N][128]: [0:64]=h2, [64:128]=o enc
__device__ float g_h[(size_t)NMAX * 64];     // layer-1 output
__device__ float g_M[(size_t)NMAX * 576];    // [N][576]: cols 0-511 = h@W2[r], cols 512-575 = h@Wroot2
__device__ float g_t2[(size_t)NMAX * 64];    // relu(cat @ Wagg + bagg)
__device__ float g_Wc1[832 * 64];            // [Wroot1 ; W1]
__device__ float g_Wc2[64 * 576];            // [W2^T per-rel | Wroot2]
// CSR
__device__ int      g_cnt[NMAX + 1];
__device__ int      g_off[NMAX + 1];
__device__ int      g_coff[NMAX + 1];
__device__ unsigned g_meta[EMAX];            // src | (r<<17)
__device__ float2   g_ea2[EMAX];             // edge_attr per sorted slot

// ---------------- packed f32x2 helpers ----------------
__device__ __forceinline__ unsigned long long bcast2(float b) {
    unsigned long long r;
    asm("mov.b64 %0, {%1, %1};" : "=l"(r) : "r"(__float_as_uint(b)));
    return r;
}
__device__ __forceinline__ void fma2(unsigned long long& d, unsigned long long a, unsigned long long b) {
    asm("fma.rn.f32x2 %0, %1, %2, %0;" : "+l"(d) : "l"(a), "l"(b));
}
__device__ __forceinline__ float lo32(unsigned long long v) { return __uint_as_float((unsigned)v); }
__device__ __forceinline__ float hi32(unsigned long long v) { return __uint_as_float((unsigned)(v >> 32)); }

// ---------------- CSR build ----------------
__global__ void k_zero_cnt(int N) {
    int i = blockIdx.x * 256 + threadIdx.x;
    if (i <= N) g_cnt[i] = 0;
}
__global__ void k_hist(const int* __restrict__ ei, int E) {
    int i = blockIdx.x * 256 + threadIdx.x;
    if (i < E) atomicAdd(&g_cnt[__ldg(ei + E + i)], 1);
}
// single-block scan: 1024 threads, each owns a contiguous chunk
__global__ void __launch_bounds__(1024) k_scan(int N, int E) {
    __shared__ int sh[1024];
    int t = threadIdx.x;
    int chunk = (N + 1023) / 1024;
    int b = t * chunk, eN = min(b + chunk, N);
    int s = 0;
    for (int i = b; i < eN; i++) s += g_cnt[i];
    sh[t] = s;
    __syncthreads();
    for (int off = 1; off < 1024; off <<= 1) {
        int v = (t >= off) ? sh[t - off] : 0;
        __syncthreads();
        sh[t] += v;
        __syncthreads();
    }
    int run = (t == 0) ? 0 : sh[t - 1];
    for (int i = b; i < eN; i++) {
        int c = g_cnt[i];
        g_off[i] = run; g_coff[i] = run;
        run += c;
    }
    if (t == 0) { g_off[N] = E; g_coff[N] = E; }
}
__global__ void k_scatter(const int* __restrict__ ei, const float* __restrict__ ea,
                          const int* __restrict__ et, int E) {
    int i = blockIdx.x * 256 + threadIdx.x;
    if (i >= E) return;
    int dst = __ldg(ei + E + i);
    int src = __ldg(ei + i);
    int r   = __ldg(et + i);
    int pos = atomicAdd(&g_coff[dst], 1);
    g_meta[pos] = (unsigned)src | ((unsigned)r << 17);
    g_ea2[pos]  = make_float2(__ldg(ea + 2 * i), __ldg(ea + 2 * i + 1));
}

// ---------------- combined weights (needs 832*64 = 53248 threads!) ----------------
__global__ void k_prep(const float* __restrict__ Wroot1, const float* __restrict__ W1,
                       const float* __restrict__ W2, const float* __restrict__ Wroot2) {
    int i = blockIdx.x * 256 + threadIdx.x;
    if (i < 832 * 64) {
        int row = i >> 6, j = i & 63;
        g_Wc1[i] = (row < 64) ? Wroot1[row * 64 + j] : W1[(row - 64) * 64 + j];
    }
    if (i < 64 * 576) {
        int k = i / 576, c = i % 576;
        float v;
        if (c < 512) { int r = c >> 6, j = c & 63; v = W2[(r * 64 + k) * 64 + j]; }
        else         { v = Wroot2[k * 64 + (c - 512)]; }
        g_Wc2[i] = v;
    }
}

// ---------------- node encoders ----------------
__global__ void k_encode(const float* __restrict__ x, const float* __restrict__ omega,
                         const float* __restrict__ Wn, const float* __restrict__ bn,
                         const float* __restrict__ Wo, const float* __restrict__ bo, int N) {
    int i = blockIdx.x * 256 + threadIdx.x;
    if (i >= N * 64) return;
    int d = i >> 6, j = i & 63;
    float x0 = __ldg(x + d * 3), x1 = __ldg(x + d * 3 + 1), x2 = __ldg(x + d * 3 + 2);
    float nv = fmaf(x0, __ldg(Wn + j), fmaf(x1, __ldg(Wn + 64 + j), fmaf(x2, __ldg(Wn + 128 + j), __ldg(bn + j))));
    g_NS[(size_t)d * 832 + j] = fmaxf(nv, 0.f);
    float o0 = __ldg(omega + d * 2), o1 = __ldg(omega + d * 2 + 1);
    float ov = fmaf(o0, __ldg(Wo + j), fmaf(o1, __ldg(Wo + 64 + j), __ldg(bo + j)));
    g_cat[(size_t)d * 128 + 64 + j] = fmaxf(ov, 0.f);
}

// ---------------- layer-1: warp per dst, register accumulate, single write ----------------
__global__ void __launch_bounds__(256) k_edge1_csr(const float* __restrict__ We,
                                                   const float* __restrict__ be, int N) {
    int gw = (blockIdx.x * 256 + threadIdx.x) >> 5;
    if (gw >= N) return;
    int lane = threadIdx.x & 31;
    int start = __ldg(g_off + gw), end = __ldg(g_off + gw + 1);

    float we0 = __ldg(We + lane), we1 = __ldg(We + 32 + lane), beL = __ldg(be + lane);
    float an0[8], an1[8], ae[8];
#pragma unroll
    for (int rr = 0; rr < 8; rr++) { an0[rr] = 0.f; an1[rr] = 0.f; ae[rr] = 0.f; }

    unsigned m = 0; float2 a = make_float2(0.f, 0.f);
    if (start < end) { m = __ldg(g_meta + start); a = __ldg(g_ea2 + start); }
    for (int e = start; e < end; e++) {
        unsigned mc = m; float2 ac = a;
        if (e + 1 < end) { m = __ldg(g_meta + e + 1); a = __ldg(g_ea2 + e + 1); }
        int src = (int)(mc & 0x1FFFFu);
        int r   = (int)(mc >> 17);
        float2 nv = *(const float2*)(g_NS + (size_t)src * 832 + lane * 2);
        float ev = fmaxf(fmaf(ac.x, we0, fmaf(ac.y, we1, beL)), 0.f);
#pragma unroll
        for (int rr = 0; rr < 8; rr++) {
            if (r == rr) { an0[rr] += nv.x; an1[rr] += nv.y; ae[rr] += ev; }
        }
    }
    float* Sd = g_NS + (size_t)gw * 832 + 64;
#pragma unroll
    for (int rr = 0; rr < 8; rr++) {
        *(float2*)(Sd + rr * 96 + lane * 2) = make_float2(an0[rr], an1[rr]);
        Sd[rr * 96 + 64 + lane] = ae[rr];
    }
}

// ---------------- layer-2: warp per dst, register max, fused combine ----------------
__global__ void __launch_bounds__(256) k_edge2_csr(const float* __restrict__ b2, int N) {
    int gw = (blockIdx.x * 256 + threadIdx.x) >> 5;
    if (gw >= N) return;
    int lane = threadIdx.x & 31;
    int start = __ldg(g_off + gw), end = __ldg(g_off + gw + 1);

    float m0[8], m1[8];
#pragma unroll
    for (int rr = 0; rr < 8; rr++) { m0[rr] = -FLT_MAX; m1[rr] = -FLT_MAX; }
    unsigned seen = 0;

    unsigned m = 0;
    if (start < end) m = __ldg(g_meta + start);
    for (int e = start; e < end; e++) {
        unsigned mc = m;
        if (e + 1 < end) m = __ldg(g_meta + e + 1);
        int src = (int)(mc & 0x1FFFFu);
        int r   = (int)(mc >> 17);
        float2 mv = *(const float2*)(g_M + (size_t)src * 576 + r * 64 + lane * 2);
        seen |= 1u << r;
#pragma unroll
        for (int rr = 0; rr < 8; rr++) {
            if (r == rr) { m0[rr] = fmaxf(m0[rr], mv.x); m1[rr] = fmaxf(m1[rr], mv.y); }
        }
    }
    float2 tmp = *(const float2*)(g_M + (size_t)gw * 576 + 512 + lane * 2);
    float s0 = tmp.x + __ldg(b2 + lane * 2);
    float s1 = tmp.y + __ldg(b2 + lane * 2 + 1);
#pragma unroll
    for (int rr = 0; rr < 8; rr++) {
        if (seen & (1u << rr)) { s0 += m0[rr]; s1 += m1[rr]; }
    }
    *(float2*)(g_cat + (size_t)gw * 128 + lane * 2) = make_float2(fmaxf(s0, 0.f), fmaxf(s1, 0.f));
}

// ---------------- tiled SGEMM: C[M,cols] = A[M,K] @ B[K,cols] (+bias, relu) ----------------
template <int NC>
__global__ void __launch_bounds__(256) k_gemm(
    const float* __restrict__ A, int lda, int K,
    const float* __restrict__ B, int ldb,
    const float* __restrict__ bias, int relu,
    float* __restrict__ C, int ldc, int M)
{
    constexpr int TN = NC / 16;
    __shared__ __align__(16) float As[16 * 66];
    __shared__ __align__(16) float Bs[16 * NC];
    int tid = threadIdx.x;
    int tx = tid & 15, ty = tid >> 4;
    int row0 = blockIdx.x * 64;
    int col0 = blockIdx.y * NC;
    unsigned long long acc[2][TN];
#pragma unroll
    for (int i = 0; i < 2; i++)
#pragma unroll
        for (int c = 0; c < TN; c++) acc[i][c] = 0ull;

    for (int kc = 0; kc < K; kc += 16) {
#pragma unroll
        for (int it = 0; it < 4; it++) {
            int idx = tid + it * 256;
            int rr = idx >> 4, k = idx & 15;
            int grow = row0 + rr;
            As[k * 66 + rr] = (grow < M) ? A[(size_t)grow * lda + kc + k] : 0.f;
        }
#pragma unroll
        for (int it = 0; it < NC / 16; it++) {
            int idx = tid + it * 256;
            int k = idx / NC, c = idx % NC;
            Bs[idx] = B[(size_t)(kc + k) * ldb + col0 + c];
        }
        __syncthreads();
#pragma unroll
        for (int k = 0; k < 16; k++) {
            unsigned long long a01 = *(const unsigned long long*)&As[k * 66 + ty * 4];
            unsigned long long a23 = *(const unsigned long long*)&As[k * 66 + ty * 4 + 2];
#pragma unroll
            for (int c0 = 0; c0 < TN; c0 += 4) {
                float4 bv = *(const float4*)&Bs[k * NC + tx * TN + c0];
                unsigned long long p0 = bcast2(bv.x), p1 = bcast2(bv.y);
                unsigned long long p2 = bcast2(bv.z), p3 = bcast2(bv.w);
                fma2(acc[0][c0 + 0], a01, p0); fma2(acc[1][c0 + 0], a23, p0);
                fma2(acc[0][c0 + 1], a01, p1); fma2(acc[1][c0 + 1], a23, p1);
                fma2(acc[0][c0 + 2], a01, p2); fma2(acc[1][c0 + 2], a23, p2);
                fma2(acc[0][c0 + 3], a01, p3); fma2(acc[1][c0 + 3], a23, p3);
            }
        }
        __syncthreads();
    }
    int colb = col0 + tx * TN;
#pragma unroll
    for (int i = 0; i < 2; i++) {
#pragma unroll
        for (int p = 0; p < 2; p++) {
            int row = row0 + ty * 4 + i * 2 + p;
            if (row >= M) continue;
#pragma unroll
            for (int c0 = 0; c0 < TN; c0 += 4) {
                float4 v;
                float* vp = (float*)&v;
#pragma unroll
                for (int cc = 0; cc < 4; cc++) {
                    unsigned long long av = acc[i][c0 + cc];
                    float f = p ? hi32(av) : lo32(av);
                    if (bias) f += __ldg(bias + colb + c0 + cc);
                    if (relu) f = fmaxf(f, 0.f);
                    vp[cc] = f;
                }
                *(float4*)&C[(size_t)row * ldc + colb + c0] = v;
            }
        }
    }
}

// ---------------- head: out = tanh(t2 . Wc + bc) * 5 ----------------
__global__ void k_f4(const float* __restrict__ Wc, const float* __restrict__ bc,
                     float* __restrict__ out, int N) {
    int w = (blockIdx.x * blockDim.x + threadIdx.x) >> 5;
    if (w >= N) return;
    int lane = threadIdx.x & 31;
    const float* t = g_t2 + (size_t)w * 64;
    float p = t[lane] * __ldg(Wc + lane) + t[lane + 32] * __ldg(Wc + lane + 32);
#pragma unroll
    for (int off = 16; off > 0; off >>= 1) p += __shfl_xor_sync(0xffffffffu, p, off);
    if (lane == 0) out[w] = tanhf(p + __ldg(bc)) * 5.f;
}

extern "C" void kernel_launch(void* const* d_in, const int* in_sizes, int n_in,
                              void* d_out, int out_size) {
    const float* x      = (const float*)d_in[0];
    const int*   ei     = (const int*)  d_in[1];
    const float* ea     = (const float*)d_in[2];
    const int*   et     = (const int*)  d_in[3];
    const float* omega  = (const float*)d_in[4];
    const float* Wn     = (const float*)d_in[5];
    const float* bn     = (const float*)d_in[6];
    const float* We     = (const float*)d_in[7];
    const float* be     = (const float*)d_in[8];
    const float* Wo     = (const float*)d_in[9];
    const float* bo     = (const float*)d_in[10];
    const float* W1     = (const float*)d_in[11];
    const float* Wroot1 = (const float*)d_in[12];
    const float* b1     = (const float*)d_in[13];
    const float* W2     = (const float*)d_in[14];
    const float* Wroot2 = (const float*)d_in[15];
    const float* b2     = (const float*)d_in[16];
    const float* Wagg   = (const float*)d_in[17];
    const float* bagg   = (const float*)d_in[18];
    const float* Wc     = (const float*)d_in[19];
    const float* bc     = (const float*)d_in[20];
    float* out = (float*)d_out;

    int N = in_sizes[0] / 3;
    int E = in_sizes[3];
    if (N > NMAX) N = NMAX;
    if (E > EMAX) E = EMAX;

    float *pNS, *ph, *pM, *pcat, *pt2, *pWc1, *pWc2;
    cudaGetSymbolAddress((void**)&pNS,  g_NS);
    cudaGetSymbolAddress((void**)&ph,   g_h);
    cudaGetSymbolAddress((void**)&pM,   g_M);
    cudaGetSymbolAddress((void**)&pcat, g_cat);
    cudaGetSymbolAddress((void**)&pt2,  g_t2);
    cudaGetSymbolAddress((void**)&pWc1, g_Wc1);
    cudaGetSymbolAddress((void**)&pWc2, g_Wc2);

    // ---- CSR build ----
    k_zero_cnt<<<(N + 256) / 256, 256>>>(N);
    k_hist<<<(E + 255) / 256, 256>>>(ei, E);
    k_scan<<<1, 1024>>>(N, E);
    k_scatter<<<(E + 255) / 256, 256>>>(ei, ea, et, E);
    // ---- weights + encoders (k_prep must cover 832*64 elements!) ----
    k_prep<<<(832 * 64 + 255) / 256, 256>>>(Wroot1, W1, W2, Wroot2);
    k_encode<<<(N * 64 + 255) / 256, 256>>>(x, omega, Wn, bn, Wo, bo, N);
    // ---- layer 1 ----
    k_edge1_csr<<<(N * 32 + 255) / 256, 256>>>(We, be, N);
    k_gemm<64><<<dim3((N + 63) / 64, 1), 256>>>(pNS, 832, 832, pWc1, 64, b1, 1, ph, 64, N);
    // ---- layer 2 ----
    k_gemm<64><<<dim3((N + 63) / 64, 9), 256>>>(ph, 64, 64, pWc2, 576, nullptr, 0, pM, 576, N);
    k_edge2_csr<<<(N * 32 + 255) / 256, 256>>>(b2, N);
    // ---- head (64 output cols -> grid.y MUST be 1) ----
    k_gemm<64><<<dim3((N + 63) / 64, 1), 256>>>(pcat, 128, 128, Wagg, 64, bagg, 1, pt2, 64, N);
    k_f4<<<(N + 7) / 8, 256>>>(Wc, bc, out, N);
}